// round 1
// baseline (speedup 1.0000x reference)
#include <cuda_runtime.h>
#include <cuda_bf16.h>

// GAT layer, N=2048 nodes, IN=1024, H=8 heads, F=32 hidden, neg_slope=0.2
//
// Pipeline:
//  K1 gemm:  g = h @ W                      (2048x1024 @ 1024x256, fp32)
//  K2 score: sl,sr per (node,head); store u1=exp(sr), u2=exp(.2 sr),
//            e1=exp(sl), e2=exp(.2 sl), thr=exp(-sl)
//  K3 attn:  per (i,h): W_ij = adj * ( u1_j>=thr_i ? e1*u1_j : e2*u2_j )
//            acc[f] += W_ij * g[j,h,f]; Z += W_ij    (no exp in inner loop)
//            j-split x8 into partial buffers (deterministic)
//  K4 norm:  out = (sum_s acc_s) / (sum_s Z_s)

#define N_NODES 2048
#define IN_F    1024
#define NH      8
#define NF      32
#define GDIM    (NH*NF)          // 256
#define NSPLIT  8
#define TI      32
#define TJ      32
#define JCHUNK  (N_NODES/NSPLIT) // 256

__device__ float g_g[N_NODES * GDIM];            // 2 MB
__device__ float g_u1[N_NODES * NH];
__device__ float g_u2[N_NODES * NH];
__device__ float g_e1[N_NODES * NH];
__device__ float g_e2[N_NODES * NH];
__device__ float g_thr[N_NODES * NH];
__device__ float g_pnum[NSPLIT][N_NODES * GDIM]; // 16.8 MB
__device__ float g_pz[NSPLIT][N_NODES * NH];

// ---------------- K1: g = h @ W  (64x64 tile, fp32) ----------------
__global__ __launch_bounds__(256) void gemm_kernel(const float* __restrict__ A,
                                                   const float* __restrict__ B) {
    __shared__ float As[16][65];
    __shared__ float Bs[16][64];
    const int tid = threadIdx.x;
    const int tx = tid & 15, ty = tid >> 4;
    const int bm = blockIdx.y << 6, bn = blockIdx.x << 6;

    float acc[4][4];
#pragma unroll
    for (int i = 0; i < 4; i++)
#pragma unroll
        for (int j = 0; j < 4; j++) acc[i][j] = 0.f;

    for (int k0 = 0; k0 < IN_F; k0 += 16) {
        {   // A tile 64x16, transposed store
            int m = tid >> 2, q = tid & 3;
            float4 v = *(const float4*)&A[(bm + m) * IN_F + k0 + q * 4];
            As[q * 4 + 0][m] = v.x;
            As[q * 4 + 1][m] = v.y;
            As[q * 4 + 2][m] = v.z;
            As[q * 4 + 3][m] = v.w;
        }
        {   // B tile 16x64
            int kk = tid >> 4, n4 = tid & 15;
            *(float4*)&Bs[kk][n4 * 4] =
                *(const float4*)&B[(k0 + kk) * GDIM + bn + n4 * 4];
        }
        __syncthreads();
#pragma unroll
        for (int kk = 0; kk < 16; kk++) {
            float a0 = As[kk][ty * 4 + 0];
            float a1 = As[kk][ty * 4 + 1];
            float a2 = As[kk][ty * 4 + 2];
            float a3 = As[kk][ty * 4 + 3];
            float4 b = *(const float4*)&Bs[kk][tx * 4];
            acc[0][0] = fmaf(a0, b.x, acc[0][0]); acc[0][1] = fmaf(a0, b.y, acc[0][1]);
            acc[0][2] = fmaf(a0, b.z, acc[0][2]); acc[0][3] = fmaf(a0, b.w, acc[0][3]);
            acc[1][0] = fmaf(a1, b.x, acc[1][0]); acc[1][1] = fmaf(a1, b.y, acc[1][1]);
            acc[1][2] = fmaf(a1, b.z, acc[1][2]); acc[1][3] = fmaf(a1, b.w, acc[1][3]);
            acc[2][0] = fmaf(a2, b.x, acc[2][0]); acc[2][1] = fmaf(a2, b.y, acc[2][1]);
            acc[2][2] = fmaf(a2, b.z, acc[2][2]); acc[2][3] = fmaf(a2, b.w, acc[2][3]);
            acc[3][0] = fmaf(a3, b.x, acc[3][0]); acc[3][1] = fmaf(a3, b.y, acc[3][1]);
            acc[3][2] = fmaf(a3, b.z, acc[3][2]); acc[3][3] = fmaf(a3, b.w, acc[3][3]);
        }
        __syncthreads();
    }
#pragma unroll
    for (int i = 0; i < 4; i++) {
        float4 v = make_float4(acc[i][0], acc[i][1], acc[i][2], acc[i][3]);
        *(float4*)&g_g[(bm + ty * 4 + i) * GDIM + bn + tx * 4] = v;
    }
}

// ---------------- K2: per-(node,head) score precompute ----------------
__global__ __launch_bounds__(256) void score_kernel(const float* __restrict__ a) {
    __shared__ float as[2 * NF];
    if (threadIdx.x < 2 * NF) as[threadIdx.x] = a[threadIdx.x];
    __syncthreads();
    const int idx = blockIdx.x * 256 + threadIdx.x;  // node*8 + h, < 16384
    const float* gp = &g_g[idx * NF];                // == g[node*256 + h*32]
    float sl = 0.f, sr = 0.f;
#pragma unroll
    for (int c = 0; c < 8; c++) {
        float4 v = *(const float4*)&gp[c * 4];
        sl = fmaf(v.x, as[c * 4 + 0], sl);
        sl = fmaf(v.y, as[c * 4 + 1], sl);
        sl = fmaf(v.z, as[c * 4 + 2], sl);
        sl = fmaf(v.w, as[c * 4 + 3], sl);
        sr = fmaf(v.x, as[NF + c * 4 + 0], sr);
        sr = fmaf(v.y, as[NF + c * 4 + 1], sr);
        sr = fmaf(v.z, as[NF + c * 4 + 2], sr);
        sr = fmaf(v.w, as[NF + c * 4 + 3], sr);
    }
    g_u1[idx]  = expf(sr);
    g_u2[idx]  = expf(0.2f * sr);
    g_e1[idx]  = expf(sl);
    g_e2[idx]  = expf(0.2f * sl);
    g_thr[idx] = expf(-sl);  // pred: sl+sr>=0  <=>  u1 >= thr
}

// ---------------- K3: fused masked-softmax aggregation ----------------
__global__ __launch_bounds__(256, 2) void attn_kernel(const int* __restrict__ adj) {
    __shared__ float gs[TJ][GDIM];   // 32 KB, head-rotated chunk layout
    __shared__ int   adjs[TI][36];   // padded stride, int4-aligned
    __shared__ float u1s[TJ][NH];
    __shared__ float u2s[TJ][NH];

    const int tid = threadIdx.x;
    const int h  = tid & 7;
    const int il = tid >> 3;
    const int i0 = blockIdx.x * TI;
    const int sp = blockIdx.y;
    const int js0 = sp * JCHUNK;
    const int ih = (i0 + il) * NH + h;

    const float e1  = g_e1[ih];
    const float e2  = g_e2[ih];
    const float thr = g_thr[ih];

    float acc[NF];
#pragma unroll
    for (int f = 0; f < NF; f++) acc[f] = 0.f;
    float Z = 0.f;

    for (int jt = 0; jt < JCHUNK; jt += TJ) {
        const int js = js0 + jt;
        __syncthreads();
        // --- load g tile with per-head chunk rotation: chunk c of head hh
        //     stored at slot (c+hh)&7 -> conflict-free reads across heads ---
#pragma unroll
        for (int l = 0; l < 8; l++) {
            int p = tid + l * 256;          // 0..2047 float4s
            int j = p >> 6;
            int rem = p & 63;               // hh*8 + c
            int hh = rem >> 3, c = rem & 7;
            float4 v = *(const float4*)&g_g[(js + j) * GDIM + (rem << 2)];
            int cc = (c + hh) & 7;
            *(float4*)&gs[j][hh * 32 + cc * 4] = v;
        }
        {   // adj tile TIxTJ
            int ila = tid >> 3, q = tid & 7;
            int4 av = *(const int4*)&adj[(i0 + ila) * N_NODES + js + q * 4];
            *(int4*)&adjs[ila][q * 4] = av;
        }
        {   // u tiles
            int jq = tid >> 3, hq = tid & 7;
            u1s[jq][hq] = g_u1[(js + jq) * NH + hq];
            u2s[jq][hq] = g_u2[(js + jq) * NH + hq];
        }
        __syncthreads();

        const float* gb  = &gs[0][h * 32];
        const int*   ab  = &adjs[il][0];
        const float* u1b = &u1s[0][h];
        const float* u2b = &u2s[0][h];
#pragma unroll 8
        for (int jj = 0; jj < TJ; jj++) {
            int   aj = ab[jj];
            float u1 = u1b[jj * NH];
            float u2 = u2b[jj * NH];
            float p1 = u1 * e1;
            float p2 = u2 * e2;
            float W = (u1 >= thr) ? p1 : p2;
            W = aj ? W : 0.f;
            Z += W;
            const float* gp = gb + jj * GDIM;
#pragma unroll
            for (int c = 0; c < 8; c++) {
                float4 v = *(const float4*)&gp[((c + h) & 7) * 4];
                acc[c * 4 + 0] = fmaf(W, v.x, acc[c * 4 + 0]);
                acc[c * 4 + 1] = fmaf(W, v.y, acc[c * 4 + 1]);
                acc[c * 4 + 2] = fmaf(W, v.z, acc[c * 4 + 2]);
                acc[c * 4 + 3] = fmaf(W, v.w, acc[c * 4 + 3]);
            }
        }
    }

    float* np = &g_pnum[sp][ih * NF];
#pragma unroll
    for (int c = 0; c < 8; c++) {
        float4 v = make_float4(acc[c * 4], acc[c * 4 + 1], acc[c * 4 + 2], acc[c * 4 + 3]);
        *(float4*)&np[c * 4] = v;
    }
    g_pz[sp][ih] = Z;
}

// ---------------- K4: combine splits + normalize ----------------
__global__ __launch_bounds__(256) void norm_kernel(float* __restrict__ out) {
    const int idx = blockIdx.x * 256 + threadIdx.x;  // < 524288
    const int ih = idx >> 5;
    float num = 0.f, z = 0.f;
#pragma unroll
    for (int s = 0; s < NSPLIT; s++) {
        num += g_pnum[s][idx];
        z   += g_pz[s][ih];
    }
    out[idx] = num / z;
}

extern "C" void kernel_launch(void* const* d_in, const int* in_sizes, int n_in,
                              void* d_out, int out_size) {
    // Defensive remap by element count (expected order: h, adj_mat, W, a)
    const float* h_ptr = nullptr;
    const int*   adj   = nullptr;
    const float* W_ptr = nullptr;
    const float* a_ptr = nullptr;
    for (int i = 0; i < n_in; i++) {
        long sz = in_sizes[i];
        if (sz == N_NODES * IN_F)          h_ptr = (const float*)d_in[i];
        else if (sz == N_NODES * N_NODES)  adj   = (const int*)d_in[i];
        else if (sz == IN_F * GDIM)        W_ptr = (const float*)d_in[i];
        else if (sz == 2 * NF)             a_ptr = (const float*)d_in[i];
    }
    float* out = (float*)d_out;

    gemm_kernel<<<dim3(GDIM / 64, N_NODES / 64), 256>>>(h_ptr, W_ptr);
    score_kernel<<<(N_NODES * NH) / 256, 256>>>(a_ptr);
    attn_kernel<<<dim3(N_NODES / TI, NSPLIT), 256>>>(adj);
    norm_kernel<<<(N_NODES * GDIM) / 256, 256>>>(out);
}

// round 2
// speedup vs baseline: 1.0019x; 1.0019x over previous
#include <cuda_runtime.h>
#include <cuda_bf16.h>

// GAT layer, N=2048 nodes, IN=1024, H=8 heads, F=32 hidden, neg_slope=0.2
//
// Pipeline:
//  K1 gemm:  g = h @ W                      (2048x1024 @ 1024x256, fp32)
//  K2 score: sl,sr per (node,head); store u1=exp(sr), u2=exp(.2 sr),
//            e1=exp(sl), e2=exp(.2 sl), thr=exp(-sl)
//  K3 attn:  per (i,h): W_ij = adj * ( u1_j>=thr_i ? e1*u1_j : e2*u2_j )
//            acc[f] += W_ij * g[j,h,f]; Z += W_ij    (no exp in inner loop)
//            j-split x8 into partial buffers (deterministic)
//  K4 norm:  out = (sum_s acc_s) / (sum_s Z_s)

#define N_NODES 2048
#define IN_F    1024
#define NH      8
#define NF      32
#define GDIM    (NH*NF)          // 256
#define NSPLIT  8
#define TI      32
#define TJ      32
#define JCHUNK  (N_NODES/NSPLIT) // 256

__device__ float g_g[N_NODES * GDIM];            // 2 MB
__device__ float g_u1[N_NODES * NH];
__device__ float g_u2[N_NODES * NH];
__device__ float g_e1[N_NODES * NH];
__device__ float g_e2[N_NODES * NH];
__device__ float g_thr[N_NODES * NH];
__device__ float g_pnum[NSPLIT][N_NODES * GDIM]; // 16.8 MB
__device__ float g_pz[NSPLIT][N_NODES * NH];

// ---------------- K1: g = h @ W  (64x64 tile, fp32) ----------------
__global__ __launch_bounds__(256) void gemm_kernel(const float* __restrict__ A,
                                                   const float* __restrict__ B) {
    __shared__ float As[16][65];
    __shared__ float Bs[16][64];
    const int tid = threadIdx.x;
    const int tx = tid & 15, ty = tid >> 4;
    const int bm = blockIdx.y << 6, bn = blockIdx.x << 6;

    float acc[4][4];
#pragma unroll
    for (int i = 0; i < 4; i++)
#pragma unroll
        for (int j = 0; j < 4; j++) acc[i][j] = 0.f;

    for (int k0 = 0; k0 < IN_F; k0 += 16) {
        {   // A tile 64x16, transposed store
            int m = tid >> 2, q = tid & 3;
            float4 v = *(const float4*)&A[(bm + m) * IN_F + k0 + q * 4];
            As[q * 4 + 0][m] = v.x;
            As[q * 4 + 1][m] = v.y;
            As[q * 4 + 2][m] = v.z;
            As[q * 4 + 3][m] = v.w;
        }
        {   // B tile 16x64
            int kk = tid >> 4, n4 = tid & 15;
            *(float4*)&Bs[kk][n4 * 4] =
                *(const float4*)&B[(k0 + kk) * GDIM + bn + n4 * 4];
        }
        __syncthreads();
#pragma unroll
        for (int kk = 0; kk < 16; kk++) {
            float a0 = As[kk][ty * 4 + 0];
            float a1 = As[kk][ty * 4 + 1];
            float a2 = As[kk][ty * 4 + 2];
            float a3 = As[kk][ty * 4 + 3];
            float4 b = *(const float4*)&Bs[kk][tx * 4];
            acc[0][0] = fmaf(a0, b.x, acc[0][0]); acc[0][1] = fmaf(a0, b.y, acc[0][1]);
            acc[0][2] = fmaf(a0, b.z, acc[0][2]); acc[0][3] = fmaf(a0, b.w, acc[0][3]);
            acc[1][0] = fmaf(a1, b.x, acc[1][0]); acc[1][1] = fmaf(a1, b.y, acc[1][1]);
            acc[1][2] = fmaf(a1, b.z, acc[1][2]); acc[1][3] = fmaf(a1, b.w, acc[1][3]);
            acc[2][0] = fmaf(a2, b.x, acc[2][0]); acc[2][1] = fmaf(a2, b.y, acc[2][1]);
            acc[2][2] = fmaf(a2, b.z, acc[2][2]); acc[2][3] = fmaf(a2, b.w, acc[2][3]);
            acc[3][0] = fmaf(a3, b.x, acc[3][0]); acc[3][1] = fmaf(a3, b.y, acc[3][1]);
            acc[3][2] = fmaf(a3, b.z, acc[3][2]); acc[3][3] = fmaf(a3, b.w, acc[3][3]);
        }
        __syncthreads();
    }
#pragma unroll
    for (int i = 0; i < 4; i++) {
        float4 v = make_float4(acc[i][0], acc[i][1], acc[i][2], acc[i][3]);
        *(float4*)&g_g[(bm + ty * 4 + i) * GDIM + bn + tx * 4] = v;
    }
}

// ---------------- K2: per-(node,head) score precompute ----------------
__global__ __launch_bounds__(256) void score_kernel(const float* __restrict__ a) {
    __shared__ float as[2 * NF];
    if (threadIdx.x < 2 * NF) as[threadIdx.x] = a[threadIdx.x];
    __syncthreads();
    const int idx = blockIdx.x * 256 + threadIdx.x;  // node*8 + h, < 16384
    const float* gp = &g_g[idx * NF];                // == g[node*256 + h*32]
    float sl = 0.f, sr = 0.f;
#pragma unroll
    for (int c = 0; c < 8; c++) {
        float4 v = *(const float4*)&gp[c * 4];
        sl = fmaf(v.x, as[c * 4 + 0], sl);
        sl = fmaf(v.y, as[c * 4 + 1], sl);
        sl = fmaf(v.z, as[c * 4 + 2], sl);
        sl = fmaf(v.w, as[c * 4 + 3], sl);
        sr = fmaf(v.x, as[NF + c * 4 + 0], sr);
        sr = fmaf(v.y, as[NF + c * 4 + 1], sr);
        sr = fmaf(v.z, as[NF + c * 4 + 2], sr);
        sr = fmaf(v.w, as[NF + c * 4 + 3], sr);
    }
    g_u1[idx]  = expf(sr);
    g_u2[idx]  = expf(0.2f * sr);
    g_e1[idx]  = expf(sl);
    g_e2[idx]  = expf(0.2f * sl);
    g_thr[idx] = expf(-sl);  // pred: sl+sr>=0  <=>  u1 >= thr
}

// ---------------- K3: fused masked-softmax aggregation ----------------
__global__ __launch_bounds__(256, 2) void attn_kernel(const int* __restrict__ adj) {
    __shared__ float gs[TJ][GDIM];   // 32 KB, head-rotated chunk layout
    __shared__ int   adjs[TI][36];   // padded stride, int4-aligned
    __shared__ float u1s[TJ][NH];
    __shared__ float u2s[TJ][NH];

    const int tid = threadIdx.x;
    const int h  = tid & 7;
    const int il = tid >> 3;
    const int i0 = blockIdx.x * TI;
    const int sp = blockIdx.y;
    const int js0 = sp * JCHUNK;
    const int ih = (i0 + il) * NH + h;

    const float e1  = g_e1[ih];
    const float e2  = g_e2[ih];
    const float thr = g_thr[ih];

    float acc[NF];
#pragma unroll
    for (int f = 0; f < NF; f++) acc[f] = 0.f;
    float Z = 0.f;

    for (int jt = 0; jt < JCHUNK; jt += TJ) {
        const int js = js0 + jt;
        __syncthreads();
        // --- load g tile with per-head chunk rotation: chunk c of head hh
        //     stored at slot (c+hh)&7 -> conflict-free reads across heads ---
#pragma unroll
        for (int l = 0; l < 8; l++) {
            int p = tid + l * 256;          // 0..2047 float4s
            int j = p >> 6;
            int rem = p & 63;               // hh*8 + c
            int hh = rem >> 3, c = rem & 7;
            float4 v = *(const float4*)&g_g[(js + j) * GDIM + (rem << 2)];
            int cc = (c + hh) & 7;
            *(float4*)&gs[j][hh * 32 + cc * 4] = v;
        }
        {   // adj tile TIxTJ
            int ila = tid >> 3, q = tid & 7;
            int4 av = *(const int4*)&adj[(i0 + ila) * N_NODES + js + q * 4];
            *(int4*)&adjs[ila][q * 4] = av;
        }
        {   // u tiles
            int jq = tid >> 3, hq = tid & 7;
            u1s[jq][hq] = g_u1[(js + jq) * NH + hq];
            u2s[jq][hq] = g_u2[(js + jq) * NH + hq];
        }
        __syncthreads();

        const float* gb  = &gs[0][h * 32];
        const int*   ab  = &adjs[il][0];
        const float* u1b = &u1s[0][h];
        const float* u2b = &u2s[0][h];
#pragma unroll 8
        for (int jj = 0; jj < TJ; jj++) {
            int   aj = ab[jj];
            float u1 = u1b[jj * NH];
            float u2 = u2b[jj * NH];
            float p1 = u1 * e1;
            float p2 = u2 * e2;
            float W = (u1 >= thr) ? p1 : p2;
            W = aj ? W : 0.f;
            Z += W;
            const float* gp = gb + jj * GDIM;
#pragma unroll
            for (int c = 0; c < 8; c++) {
                float4 v = *(const float4*)&gp[((c + h) & 7) * 4];
                acc[c * 4 + 0] = fmaf(W, v.x, acc[c * 4 + 0]);
                acc[c * 4 + 1] = fmaf(W, v.y, acc[c * 4 + 1]);
                acc[c * 4 + 2] = fmaf(W, v.z, acc[c * 4 + 2]);
                acc[c * 4 + 3] = fmaf(W, v.w, acc[c * 4 + 3]);
            }
        }
    }

    float* np = &g_pnum[sp][ih * NF];
#pragma unroll
    for (int c = 0; c < 8; c++) {
        float4 v = make_float4(acc[c * 4], acc[c * 4 + 1], acc[c * 4 + 2], acc[c * 4 + 3]);
        *(float4*)&np[c * 4] = v;
    }
    g_pz[sp][ih] = Z;
}

// ---------------- K4: combine splits + normalize ----------------
__global__ __launch_bounds__(256) void norm_kernel(float* __restrict__ out) {
    const int idx = blockIdx.x * 256 + threadIdx.x;  // < 524288
    const int ih = idx >> 5;
    float num = 0.f, z = 0.f;
#pragma unroll
    for (int s = 0; s < NSPLIT; s++) {
        num += g_pnum[s][idx];
        z   += g_pz[s][ih];
    }
    out[idx] = num / z;
}

extern "C" void kernel_launch(void* const* d_in, const int* in_sizes, int n_in,
                              void* d_out, int out_size) {
    // Defensive remap by element count (expected order: h, adj_mat, W, a)
    const float* h_ptr = nullptr;
    const int*   adj   = nullptr;
    const float* W_ptr = nullptr;
    const float* a_ptr = nullptr;
    for (int i = 0; i < n_in; i++) {
        long sz = in_sizes[i];
        if (sz == N_NODES * IN_F)          h_ptr = (const float*)d_in[i];
        else if (sz == N_NODES * N_NODES)  adj   = (const int*)d_in[i];
        else if (sz == IN_F * GDIM)        W_ptr = (const float*)d_in[i];
        else if (sz == 2 * NF)             a_ptr = (const float*)d_in[i];
    }
    float* out = (float*)d_out;

    gemm_kernel<<<dim3(GDIM / 64, N_NODES / 64), 256>>>(h_ptr, W_ptr);
    score_kernel<<<(N_NODES * NH) / 256, 256>>>(a_ptr);
    attn_kernel<<<dim3(N_NODES / TI, NSPLIT), 256>>>(adj);
    norm_kernel<<<(N_NODES * GDIM) / 256, 256>>>(out);
}

// round 4
// speedup vs baseline: 2.1551x; 2.1509x over previous
#include <cuda_runtime.h>
#include <cuda_fp16.h>
#include <cuda_bf16.h>
#include <cstdint>

// GAT N=2048, IN=1024, H=8, F=32, slope=0.2 — HMMA (mma.sync) aggregation.
//  K1 gemm:    g = h @ W (fp32 SIMT, exact)
//  K2 score:   u1=exp(sr),u2=exp(.2sr),e1=exp(sl),e2=exp(.2sl),thr=exp(-sl), [h][node]
//  K3 bfrag:   pre-pack gT (hi/lo fp16) into mma.sync B-fragment layout, 40 N-rows
//              (f 0..31 = g, f32 = ones -> Z column, f33..39 = 0)
//  K4 adjbits: adj int32 -> bitmask [2048][64] words
//  K5 attn:    W generated in A-fragment registers (no exp), mma.sync m16n8k16
//  K6 norm:    out = sum(num)/sum(Z)

#define N_NODES 2048
#define IN_F    1024
#define NH      8
#define NF      32
#define GDIM    256
#define NSPLIT  4
#define JSPAN   (N_NODES/NSPLIT)   // 512

__device__ float  g_g[N_NODES * GDIM];
__device__ float  g_u1T[NH * N_NODES];
__device__ float  g_u2T[NH * N_NODES];
__device__ float  g_e1T[NH * N_NODES];
__device__ float  g_e2T[NH * N_NODES];
__device__ float  g_thrT[NH * N_NODES];
// B fragments: [h][jg(128)][nf(5)][lane(32)] uint2 (reg0,reg1)
__device__ uint2  g_bfragHI[NH * 128 * 5 * 32];
__device__ uint2  g_bfragLO[NH * 128 * 5 * 32];
__device__ uint32_t g_adjbits[N_NODES * (N_NODES / 32)];
__device__ float  g_pnum[NSPLIT][N_NODES * GDIM];
__device__ float  g_pz[NSPLIT][N_NODES * NH];

__device__ __forceinline__ uint32_t h2u(__half2 v) { return *(uint32_t*)&v; }

__device__ __forceinline__ void mma16816(float* c, const uint32_t* a, const uint2 b) {
    asm volatile(
        "mma.sync.aligned.m16n8k16.row.col.f32.f16.f16.f32 "
        "{%0,%1,%2,%3}, {%4,%5,%6,%7}, {%8,%9}, {%0,%1,%2,%3};"
        : "+f"(c[0]), "+f"(c[1]), "+f"(c[2]), "+f"(c[3])
        : "r"(a[0]), "r"(a[1]), "r"(a[2]), "r"(a[3]), "r"(b.x), "r"(b.y));
}

// ---------------- K1: g = h @ W (fp32, 64x64 tile) ----------------
__global__ __launch_bounds__(256) void gemm_kernel(const float* __restrict__ A,
                                                   const float* __restrict__ B) {
    __shared__ float As[16][65];
    __shared__ float Bs[16][64];
    const int tid = threadIdx.x;
    const int tx = tid & 15, ty = tid >> 4;
    const int bm = blockIdx.y << 6, bn = blockIdx.x << 6;
    float acc[4][4];
#pragma unroll
    for (int i = 0; i < 4; i++)
#pragma unroll
        for (int j = 0; j < 4; j++) acc[i][j] = 0.f;
    for (int k0 = 0; k0 < IN_F; k0 += 16) {
        {
            int m = tid >> 2, q = tid & 3;
            float4 v = *(const float4*)&A[(bm + m) * IN_F + k0 + q * 4];
            As[q*4+0][m] = v.x; As[q*4+1][m] = v.y; As[q*4+2][m] = v.z; As[q*4+3][m] = v.w;
        }
        {
            int kk = tid >> 4, n4 = tid & 15;
            *(float4*)&Bs[kk][n4*4] = *(const float4*)&B[(k0+kk)*GDIM + bn + n4*4];
        }
        __syncthreads();
#pragma unroll
        for (int kk = 0; kk < 16; kk++) {
            float a0 = As[kk][ty*4+0], a1 = As[kk][ty*4+1];
            float a2 = As[kk][ty*4+2], a3 = As[kk][ty*4+3];
            float4 b = *(const float4*)&Bs[kk][tx*4];
            acc[0][0]=fmaf(a0,b.x,acc[0][0]); acc[0][1]=fmaf(a0,b.y,acc[0][1]);
            acc[0][2]=fmaf(a0,b.z,acc[0][2]); acc[0][3]=fmaf(a0,b.w,acc[0][3]);
            acc[1][0]=fmaf(a1,b.x,acc[1][0]); acc[1][1]=fmaf(a1,b.y,acc[1][1]);
            acc[1][2]=fmaf(a1,b.z,acc[1][2]); acc[1][3]=fmaf(a1,b.w,acc[1][3]);
            acc[2][0]=fmaf(a2,b.x,acc[2][0]); acc[2][1]=fmaf(a2,b.y,acc[2][1]);
            acc[2][2]=fmaf(a2,b.z,acc[2][2]); acc[2][3]=fmaf(a2,b.w,acc[2][3]);
            acc[3][0]=fmaf(a3,b.x,acc[3][0]); acc[3][1]=fmaf(a3,b.y,acc[3][1]);
            acc[3][2]=fmaf(a3,b.z,acc[3][2]); acc[3][3]=fmaf(a3,b.w,acc[3][3]);
        }
        __syncthreads();
    }
#pragma unroll
    for (int i = 0; i < 4; i++) {
        float4 v = make_float4(acc[i][0], acc[i][1], acc[i][2], acc[i][3]);
        *(float4*)&g_g[(bm + ty*4 + i) * GDIM + bn + tx*4] = v;
    }
}

// ---------------- K2: score precompute (transposed) ----------------
__global__ __launch_bounds__(256) void score_kernel(const float* __restrict__ a) {
    __shared__ float as[2 * NF];
    if (threadIdx.x < 2 * NF) as[threadIdx.x] = a[threadIdx.x];
    __syncthreads();
    const int idx = blockIdx.x * 256 + threadIdx.x;   // node*8 + h
    const int node = idx >> 3, h = idx & 7;
    const float* gp = &g_g[idx * NF];
    float sl = 0.f, sr = 0.f;
#pragma unroll
    for (int c = 0; c < 8; c++) {
        float4 v = *(const float4*)&gp[c * 4];
        sl = fmaf(v.x, as[c*4+0], sl); sl = fmaf(v.y, as[c*4+1], sl);
        sl = fmaf(v.z, as[c*4+2], sl); sl = fmaf(v.w, as[c*4+3], sl);
        sr = fmaf(v.x, as[NF+c*4+0], sr); sr = fmaf(v.y, as[NF+c*4+1], sr);
        sr = fmaf(v.z, as[NF+c*4+2], sr); sr = fmaf(v.w, as[NF+c*4+3], sr);
    }
    const int o = h * N_NODES + node;
    g_u1T[o]  = expf(sr);
    g_u2T[o]  = expf(0.2f * sr);
    g_e1T[o]  = expf(sl);
    g_e2T[o]  = expf(0.2f * sl);
    g_thrT[o] = expf(-sl);
}

// ---------------- K3: pack g into B-fragment layout (hi/lo fp16) ----------------
// idx -> (h, jg, nf, lane). Fragment m16n8k16 B (col): reg r holds
// halves { B[k0][n], B[k0+1][n] } with k0 = r*8 + (lane%4)*2, n = lane>>4... n = lane/4.
__global__ __launch_bounds__(256) void bfrag_kernel() {
    int idx = blockIdx.x * 256 + threadIdx.x;          // < 163840
    int lane = idx & 31;
    int rem = idx >> 5;
    int nf = rem % 5; rem /= 5;
    int jg = rem & 127;
    int h  = rem >> 7;
    int n = lane >> 2;
    int f = nf * 8 + n;
    int kq = (lane & 3) * 2;
    int j0 = jg * 16;

    float v[4];   // r=0: k0,k0+1 ; r=1: k0+8,k0+9
#pragma unroll
    for (int r = 0; r < 2; r++)
#pragma unroll
        for (int s = 0; s < 2; s++) {
            int j = j0 + r * 8 + kq + s;
            float val;
            if (f < NF)        val = g_g[j * GDIM + h * NF + f];
            else if (f == NF)  val = 1.0f;
            else               val = 0.0f;
            v[r * 2 + s] = val;
        }
    __half h0 = __float2half_rn(v[0]), h1 = __float2half_rn(v[1]);
    __half h2 = __float2half_rn(v[2]), h3 = __float2half_rn(v[3]);
    __half l0 = __float2half_rn(v[0] - __half2float(h0));
    __half l1 = __float2half_rn(v[1] - __half2float(h1));
    __half l2 = __float2half_rn(v[2] - __half2float(h2));
    __half l3 = __float2half_rn(v[3] - __half2float(h3));
    g_bfragHI[idx] = make_uint2(h2u(__halves2half2(h0, h1)), h2u(__halves2half2(h2, h3)));
    g_bfragLO[idx] = make_uint2(h2u(__halves2half2(l0, l1)), h2u(__halves2half2(l2, l3)));
}

// ---------------- K4: adjacency -> bitmask words ----------------
__global__ __launch_bounds__(256) void adjbits_kernel(const int* __restrict__ adj) {
    int idx = blockIdx.x * 256 + threadIdx.x;          // row*64 + w, < 131072
    const int4* ap = (const int4*)&adj[(long)idx * 32];
    uint32_t m = 0;
#pragma unroll
    for (int q = 0; q < 8; q++) {
        int4 av = ap[q];
        m |= (av.x ? 1u : 0u) << (q * 4 + 0);
        m |= (av.y ? 1u : 0u) << (q * 4 + 1);
        m |= (av.z ? 1u : 0u) << (q * 4 + 2);
        m |= (av.w ? 1u : 0u) << (q * 4 + 3);
    }
    g_adjbits[idx] = m;
}

// ---------------- K5: HMMA attention aggregation ----------------
// CTA: 128 i-rows x 4 heads x 512 j. 8 warps: warp w -> head w>>1, i-half (w&1)*64.
// Per warp: C[64 x 40] fp32 = 4 mfrag x 5 nfrag. A = W tile built in registers.
__global__ __launch_bounds__(256, 1) void attn_kernel() {
    __shared__ uint32_t adjw[128];
    __shared__ float u1s[128];   // [4 h][32 j]
    __shared__ float u2s[128];

    const int tid = threadIdx.x, wid = tid >> 5, lane = tid & 31;
    const int i0 = blockIdx.x * 128;
    const int hg = blockIdx.y;
    const int sp = blockIdx.z;
    const int j00 = sp * JSPAN;

    const int hloc  = wid >> 1;
    const int hglob = hg * 4 + hloc;
    const int ihalf = (wid & 1) * 64;
    const int rq = lane >> 2;          // row-in-frag 0..7
    const int kq = (lane & 3) * 2;     // k/n quad offset

    // per-row scalars (rows fixed for the whole kernel)
    float e1r[4][2], e2r[4][2], thr[4][2];
#pragma unroll
    for (int mf = 0; mf < 4; mf++) {
        int r = i0 + ihalf + mf * 16 + rq;
        e1r[mf][0] = g_e1T[hglob * N_NODES + r];
        e1r[mf][1] = g_e1T[hglob * N_NODES + r + 8];
        e2r[mf][0] = g_e2T[hglob * N_NODES + r];
        e2r[mf][1] = g_e2T[hglob * N_NODES + r + 8];
        thr[mf][0] = g_thrT[hglob * N_NODES + r];
        thr[mf][1] = g_thrT[hglob * N_NODES + r + 8];
    }

    float acc[4][5][4];
#pragma unroll
    for (int mf = 0; mf < 4; mf++)
#pragma unroll
        for (int nf = 0; nf < 5; nf++)
#pragma unroll
            for (int q = 0; q < 4; q++) acc[mf][nf][q] = 0.f;

    for (int c = 0; c < 16; c++) {
        const int j0c = j00 + c * 32;
        __syncthreads();
        if (tid < 128) {
            adjw[tid] = g_adjbits[(i0 + tid) * (N_NODES / 32) + (j0c >> 5)];
            u1s[tid] = g_u1T[(hg * 4 + (tid >> 5)) * N_NODES + j0c + (tid & 31)];
        } else {
            int q = tid - 128;
            u2s[q] = g_u2T[(hg * 4 + (q >> 5)) * N_NODES + j0c + (q & 31)];
        }
        __syncthreads();

#pragma unroll
        for (int kstep = 0; kstep < 2; kstep++) {
            const int jg = (j0c >> 4) + kstep;       // global 16-j group
            uint2 bh[5], bl[5];
            const long bbase = ((long)(hglob * 128 + jg) * 5) * 32 + lane;
#pragma unroll
            for (int nf = 0; nf < 5; nf++) {
                bh[nf] = g_bfragHI[bbase + nf * 32];
                bl[nf] = g_bfragLO[bbase + nf * 32];
            }
            // u values for this warp's 4 j positions (same for all mf)
            const int jb = kstep * 16 + kq;
            float u1_0 = u1s[hloc * 32 + jb + 0];
            float u1_1 = u1s[hloc * 32 + jb + 1];
            float u1_8 = u1s[hloc * 32 + jb + 8];
            float u1_9 = u1s[hloc * 32 + jb + 9];
            float u2_0 = u2s[hloc * 32 + jb + 0];
            float u2_1 = u2s[hloc * 32 + jb + 1];
            float u2_8 = u2s[hloc * 32 + jb + 8];
            float u2_9 = u2s[hloc * 32 + jb + 9];

#pragma unroll
            for (int mf = 0; mf < 4; mf++) {
                uint32_t aw0 = adjw[ihalf + mf * 16 + rq];
                uint32_t aw1 = adjw[ihalf + mf * 16 + rq + 8];
                uint32_t areg[4];
#pragma unroll
                for (int rowsel = 0; rowsel < 2; rowsel++) {
                    float e1 = e1r[mf][rowsel], e2 = e2r[mf][rowsel], th = thr[mf][rowsel];
                    uint32_t aw = rowsel ? aw1 : aw0;
                    float w0 = (u1_0 >= th) ? u1_0 * e1 : u2_0 * e2;
                    float w1 = (u1_1 >= th) ? u1_1 * e1 : u2_1 * e2;
                    float w8 = (u1_8 >= th) ? u1_8 * e1 : u2_8 * e2;
                    float w9 = (u1_9 >= th) ? u1_9 * e1 : u2_9 * e2;
                    w0 = ((aw >> (jb + 0)) & 1) ? w0 : 0.f;
                    w1 = ((aw >> (jb + 1)) & 1) ? w1 : 0.f;
                    w8 = ((aw >> (jb + 8)) & 1) ? w8 : 0.f;
                    w9 = ((aw >> (jb + 9)) & 1) ? w9 : 0.f;
                    areg[rowsel]     = h2u(__floats2half2_rn(w0, w1));
                    areg[rowsel + 2] = h2u(__floats2half2_rn(w8, w9));
                }
#pragma unroll
                for (int nf = 0; nf < 5; nf++) {
                    mma16816(acc[mf][nf], areg, bh[nf]);
                    mma16816(acc[mf][nf], areg, bl[nf]);
                }
            }
        }
    }

    // epilogue: C frag (row lane>>2 (+8), col (lane&3)*2 (+1))
#pragma unroll
    for (int mf = 0; mf < 4; mf++) {
        int r0 = i0 + ihalf + mf * 16 + rq;
        int r1 = r0 + 8;
#pragma unroll
        for (int nf = 0; nf < 4; nf++) {
            int f = nf * 8 + kq;
            *(float2*)&g_pnum[sp][r0 * GDIM + hglob * NF + f] =
                make_float2(acc[mf][nf][0], acc[mf][nf][1]);
            *(float2*)&g_pnum[sp][r1 * GDIM + hglob * NF + f] =
                make_float2(acc[mf][nf][2], acc[mf][nf][3]);
        }
        if ((lane & 3) == 0) {   // col 32 = Z
            g_pz[sp][r0 * NH + hglob] = acc[mf][4][0];
            g_pz[sp][r1 * NH + hglob] = acc[mf][4][2];
        }
    }
}

// ---------------- K6: combine + normalize ----------------
__global__ __launch_bounds__(256) void norm_kernel(float* __restrict__ out) {
    const int idx = blockIdx.x * 256 + threadIdx.x;
    const int ih = idx >> 5;
    float num = 0.f, z = 0.f;
#pragma unroll
    for (int s = 0; s < NSPLIT; s++) {
        num += g_pnum[s][idx];
        z   += g_pz[s][ih];
    }
    out[idx] = num / z;
}

extern "C" void kernel_launch(void* const* d_in, const int* in_sizes, int n_in,
                              void* d_out, int out_size) {
    const float* h_ptr = nullptr;
    const int*   adj   = nullptr;
    const float* W_ptr = nullptr;
    const float* a_ptr = nullptr;
    for (int i = 0; i < n_in; i++) {
        long sz = in_sizes[i];
        if (sz == (long)N_NODES * IN_F)          h_ptr = (const float*)d_in[i];
        else if (sz == (long)N_NODES * N_NODES)  adj   = (const int*)d_in[i];
        else if (sz == (long)IN_F * GDIM)        W_ptr = (const float*)d_in[i];
        else if (sz == 2 * NF)                   a_ptr = (const float*)d_in[i];
    }
    float* out = (float*)d_out;

    gemm_kernel<<<dim3(GDIM / 64, N_NODES / 64), 256>>>(h_ptr, W_ptr);
    score_kernel<<<(N_NODES * NH) / 256, 256>>>(a_ptr);
    bfrag_kernel<<<(NH * 128 * 5 * 32) / 256, 256>>>();
    adjbits_kernel<<<(N_NODES * (N_NODES / 32)) / 256, 256>>>(adj);
    attn_kernel<<<dim3(N_NODES / 128, 2, NSPLIT), 256>>>();
    norm_kernel<<<(N_NODES * GDIM) / 256, 256>>>(out);
}

// round 7
// speedup vs baseline: 2.7195x; 1.2619x over previous
#include <cuda_runtime.h>
#include <cuda_fp16.h>
#include <cuda_bf16.h>
#include <cstdint>

// GAT N=2048, IN=1024, H=8, F=32, slope=0.2 — all-HMMA pipeline.
//  K1 hgemm:   g = h @ W, split-fp16 (hi/lo, 3 passes) HMMA -> fp32-accurate g
//  K2 score:   u1=exp(sr),u2=exp(.2sr),e1=exp(sl),e2=exp(.2sl),thr=exp(-sl), [h][node]
//  K3 bfrag:   pack gT fp16 (hi only) into mma B-fragment layout, 40 N-rows
//              (f 0..31 = g, f32 = ones -> Z column, f33..39 = 0)
//  K4 adjbits: adj int32 -> bitmask words via ballot
//  K5 attn:    W built in A-fragment registers (no exp), mma.sync m16n8k16
//  K6 norm:    out = sum(num)/sum(Z), float4 per thread

#define N_NODES 2048
#define IN_F    1024
#define NH      8
#define NF      32
#define GDIM    256
#define NSPLIT  4
#define JSPAN   (N_NODES/NSPLIT)   // 512

__device__ float  g_g[N_NODES * GDIM];
__device__ float  g_u1T[NH * N_NODES];
__device__ float  g_u2T[NH * N_NODES];
__device__ float  g_e1T[NH * N_NODES];
__device__ float  g_e2T[NH * N_NODES];
__device__ float  g_thrT[NH * N_NODES];
__device__ uint2  g_bfragHI[NH * 128 * 5 * 32];
__device__ uint32_t g_adjbits[N_NODES * (N_NODES / 32)];
__device__ float  g_pnum[NSPLIT][N_NODES * GDIM];
__device__ float  g_pz[NSPLIT][N_NODES * NH];

__device__ __forceinline__ uint32_t h2u(__half2 v) { return *(uint32_t*)&v; }

__device__ __forceinline__ void mma16816(float* c, const uint32_t* a, const uint2 b) {
    asm volatile(
        "mma.sync.aligned.m16n8k16.row.col.f32.f16.f16.f32 "
        "{%0,%1,%2,%3}, {%4,%5,%6,%7}, {%8,%9}, {%0,%1,%2,%3};"
        : "+f"(c[0]), "+f"(c[1]), "+f"(c[2]), "+f"(c[3])
        : "r"(a[0]), "r"(a[1]), "r"(a[2]), "r"(a[3]), "r"(b.x), "r"(b.y));
}

// ---------------- K1: g = h @ W, split-fp16 HMMA ----------------
// CTA tile 64x64, K-chunk 32, 128 threads (4 warps, 2x2), double-buffered smem.
// Smem layouts (per buffer), fragment-native:
//   Ah/Al: [ksub2][mf4][lane32][reg4]  half2   (4 KB each)
//   Bh/Bl: [ksub2][nf8][lane32][reg2]  half2   (4 KB each)
__global__ __launch_bounds__(128) void hgemm_kernel(const float* __restrict__ A,
                                                    const float* __restrict__ B) {
    __shared__ __half2 Ah[2][2*4*32*4], Al[2][2*4*32*4];
    __shared__ __half2 Bh[2][2*8*32*2], Bl[2][2*8*32*2];

    const int tid = threadIdx.x, wid = tid >> 5, lane = tid & 31;
    const int bm = blockIdx.y << 6, bn = blockIdx.x << 6;
    const int wm = wid & 1, wn = wid >> 1;

    // A loader mapping: row = tid>>1 (0..63), kh = (tid&1)*16
    const int arow = tid >> 1, akh = (tid & 1) * 16;
    const int amf = arow >> 4, ag8 = arow & 7, amh = (arow >> 3) & 1;
    const int aksub = tid & 1;
    // B loader mapping: kp = tid&15 (k=2kp), n8 = tid>>4
    const int bkp = tid & 15, bn8 = tid >> 4;
    const int bksub = bkp >> 3, breg = (bkp >> 2) & 1, blq = bkp & 3;

    float fa[16], fb[16];
    auto ldgA = [&](int k0) {
        const float* p = &A[(bm + arow) * IN_F + k0 + akh];
        float4 v0 = *(const float4*)p;
        float4 v1 = *(const float4*)(p + 4);
        float4 v2 = *(const float4*)(p + 8);
        float4 v3 = *(const float4*)(p + 12);
        fa[0]=v0.x; fa[1]=v0.y; fa[2]=v0.z; fa[3]=v0.w;
        fa[4]=v1.x; fa[5]=v1.y; fa[6]=v1.z; fa[7]=v1.w;
        fa[8]=v2.x; fa[9]=v2.y; fa[10]=v2.z; fa[11]=v2.w;
        fa[12]=v3.x; fa[13]=v3.y; fa[14]=v3.z; fa[15]=v3.w;
    };
    auto ldgB = [&](int k0) {
        const float* p0 = &B[(k0 + 2*bkp) * GDIM + bn + bn8 * 8];
        const float* p1 = p0 + GDIM;
        float4 v0 = *(const float4*)p0;
        float4 v1 = *(const float4*)(p0 + 4);
        float4 v2 = *(const float4*)p1;
        float4 v3 = *(const float4*)(p1 + 4);
        fb[0]=v0.x; fb[1]=v0.y; fb[2]=v0.z; fb[3]=v0.w;
        fb[4]=v1.x; fb[5]=v1.y; fb[6]=v1.z; fb[7]=v1.w;
        fb[8]=v2.x; fb[9]=v2.y; fb[10]=v2.z; fb[11]=v2.w;
        fb[12]=v3.x; fb[13]=v3.y; fb[14]=v3.z; fb[15]=v3.w;
    };
    auto sts = [&](int buf) {
        // A: 8 half2 hi + 8 lo. kk = 0..15 pairs
#pragma unroll
        for (int kk = 0; kk < 16; kk += 2) {
            float v0 = fa[kk], v1 = fa[kk + 1];
            __half hh0 = __float2half_rn(v0), hh1 = __float2half_rn(v1);
            __half hl0 = __float2half_rn(v0 - __half2float(hh0));
            __half hl1 = __float2half_rn(v1 - __half2float(hh1));
            int reg = amh + ((kk >= 8) ? 2 : 0);
            int ln  = ag8 * 4 + ((kk & 7) >> 1);
            int idx = ((aksub * 4 + amf) * 32 + ln) * 4 + reg;
            Ah[buf][idx] = __halves2half2(hh0, hh1);
            Al[buf][idx] = __halves2half2(hl0, hl1);
        }
        // B: for n 0..7: half2 = (B[k][n], B[k+1][n])
#pragma unroll
        for (int n = 0; n < 8; n++) {
            float v0 = fb[n], v1 = fb[8 + n];
            __half hh0 = __float2half_rn(v0), hh1 = __float2half_rn(v1);
            __half hl0 = __float2half_rn(v0 - __half2float(hh0));
            __half hl1 = __float2half_rn(v1 - __half2float(hh1));
            int ln  = n * 4 + blq;
            int idx = ((bksub * 8 + bn8) * 32 + ln) * 2 + breg;
            Bh[buf][idx] = __halves2half2(hh0, hh1);
            Bl[buf][idx] = __halves2half2(hl0, hl1);
        }
    };

    float acc[2][4][4];
#pragma unroll
    for (int mf = 0; mf < 2; mf++)
#pragma unroll
        for (int nf = 0; nf < 4; nf++)
#pragma unroll
            for (int q = 0; q < 4; q++) acc[mf][nf][q] = 0.f;

    ldgA(0); ldgB(0);
    sts(0);

    for (int c = 0; c < IN_F / 32; c++) {
        __syncthreads();
        const int buf = c & 1;
        if (c + 1 < IN_F / 32) { ldgA((c + 1) * 32); ldgB((c + 1) * 32); }
#pragma unroll
        for (int ks = 0; ks < 2; ks++) {
            uint4 ahi[2], alo[2];
            uint2 bhi[4], blo[4];
#pragma unroll
            for (int mf = 0; mf < 2; mf++) {
                int idx = ((ks * 4 + wm * 2 + mf) * 32 + lane) * 4;
                ahi[mf] = *(uint4*)&Ah[buf][idx];
                alo[mf] = *(uint4*)&Al[buf][idx];
            }
#pragma unroll
            for (int nf = 0; nf < 4; nf++) {
                int idx = ((ks * 8 + wn * 4 + nf) * 32 + lane) * 2;
                bhi[nf] = *(uint2*)&Bh[buf][idx];
                blo[nf] = *(uint2*)&Bl[buf][idx];
            }
#pragma unroll
            for (int mf = 0; mf < 2; mf++) {
                uint32_t ah[4] = {ahi[mf].x, ahi[mf].y, ahi[mf].z, ahi[mf].w};
                uint32_t al[4] = {alo[mf].x, alo[mf].y, alo[mf].z, alo[mf].w};
#pragma unroll
                for (int nf = 0; nf < 4; nf++) {
                    mma16816(acc[mf][nf], ah, bhi[nf]);
                    mma16816(acc[mf][nf], ah, blo[nf]);
                    mma16816(acc[mf][nf], al, bhi[nf]);
                }
            }
        }
        if (c + 1 < IN_F / 32) sts((c + 1) & 1);
    }

    const int rq = lane >> 2, cq = (lane & 3) * 2;
#pragma unroll
    for (int mf = 0; mf < 2; mf++) {
        int r0 = bm + (wm * 2 + mf) * 16 + rq;
#pragma unroll
        for (int nf = 0; nf < 4; nf++) {
            int col = bn + (wn * 4 + nf) * 8 + cq;
            *(float2*)&g_g[r0 * GDIM + col] = make_float2(acc[mf][nf][0], acc[mf][nf][1]);
            *(float2*)&g_g[(r0 + 8) * GDIM + col] = make_float2(acc[mf][nf][2], acc[mf][nf][3]);
        }
    }
}

// ---------------- K2: score precompute (transposed) ----------------
__global__ __launch_bounds__(256) void score_kernel(const float* __restrict__ a) {
    __shared__ float as[2 * NF];
    if (threadIdx.x < 2 * NF) as[threadIdx.x] = a[threadIdx.x];
    __syncthreads();
    const int idx = blockIdx.x * 256 + threadIdx.x;   // node*8 + h
    const int node = idx >> 3, h = idx & 7;
    const float* gp = &g_g[idx * NF];
    float sl = 0.f, sr = 0.f;
#pragma unroll
    for (int c = 0; c < 8; c++) {
        float4 v = *(const float4*)&gp[c * 4];
        sl = fmaf(v.x, as[c*4+0], sl); sl = fmaf(v.y, as[c*4+1], sl);
        sl = fmaf(v.z, as[c*4+2], sl); sl = fmaf(v.w, as[c*4+3], sl);
        sr = fmaf(v.x, as[NF+c*4+0], sr); sr = fmaf(v.y, as[NF+c*4+1], sr);
        sr = fmaf(v.z, as[NF+c*4+2], sr); sr = fmaf(v.w, as[NF+c*4+3], sr);
    }
    const int o = h * N_NODES + node;
    g_u1T[o]  = expf(sr);
    g_u2T[o]  = expf(0.2f * sr);
    g_e1T[o]  = expf(sl);
    g_e2T[o]  = expf(0.2f * sl);
    g_thrT[o] = expf(-sl);
}

// ---------------- K3: pack g into B-fragment layout (hi fp16) ----------------
__global__ __launch_bounds__(256) void bfrag_kernel() {
    int idx = blockIdx.x * 256 + threadIdx.x;          // < 163840
    int lane = idx & 31;
    int rem = idx >> 5;
    int nf = rem % 5; rem /= 5;
    int jg = rem & 127;
    int h  = rem >> 7;
    int n = lane >> 2;
    int f = nf * 8 + n;
    int kq = (lane & 3) * 2;
    int j0 = jg * 16;

    float v[4];
#pragma unroll
    for (int r = 0; r < 2; r++)
#pragma unroll
        for (int s = 0; s < 2; s++) {
            int j = j0 + r * 8 + kq + s;
            float val;
            if (f < NF)        val = g_g[j * GDIM + h * NF + f];
            else if (f == NF)  val = 1.0f;
            else               val = 0.0f;
            v[r * 2 + s] = val;
        }
    g_bfragHI[idx] = make_uint2(
        h2u(__halves2half2(__float2half_rn(v[0]), __float2half_rn(v[1]))),
        h2u(__halves2half2(__float2half_rn(v[2]), __float2half_rn(v[3]))));
}

// ---------------- K4: adjacency -> bitmask words (ballot) ----------------
__global__ __launch_bounds__(256) void adjbits_kernel(const int* __restrict__ adj) {
    int e = blockIdx.x * 256 + threadIdx.x;            // element index
    int v = adj[e];
    uint32_t m = __ballot_sync(0xFFFFFFFFu, v != 0);
    if ((threadIdx.x & 31) == 0) g_adjbits[e >> 5] = m;
}

// ---------------- K5: HMMA attention aggregation ----------------
__global__ __launch_bounds__(256, 1) void attn_kernel() {
    __shared__ uint32_t adjw[128];
    __shared__ float u1s[128];   // [4 h][32 j]
    __shared__ float u2s[128];

    const int tid = threadIdx.x, wid = tid >> 5, lane = tid & 31;
    const int i0 = blockIdx.x * 128;
    const int hg = blockIdx.y;
    const int sp = blockIdx.z;
    const int j00 = sp * JSPAN;

    const int hloc  = wid >> 1;
    const int hglob = hg * 4 + hloc;
    const int ihalf = (wid & 1) * 64;
    const int rq = lane >> 2;
    const int kq = (lane & 3) * 2;

    float e1r[4][2], e2r[4][2], thr[4][2];
#pragma unroll
    for (int mf = 0; mf < 4; mf++) {
        int r = i0 + ihalf + mf * 16 + rq;
        e1r[mf][0] = g_e1T[hglob * N_NODES + r];
        e1r[mf][1] = g_e1T[hglob * N_NODES + r + 8];
        e2r[mf][0] = g_e2T[hglob * N_NODES + r];
        e2r[mf][1] = g_e2T[hglob * N_NODES + r + 8];
        thr[mf][0] = g_thrT[hglob * N_NODES + r];
        thr[mf][1] = g_thrT[hglob * N_NODES + r + 8];
    }

    float acc[4][5][4];
#pragma unroll
    for (int mf = 0; mf < 4; mf++)
#pragma unroll
        for (int nf = 0; nf < 5; nf++)
#pragma unroll
            for (int q = 0; q < 4; q++) acc[mf][nf][q] = 0.f;

    for (int c = 0; c < 16; c++) {
        const int j0c = j00 + c * 32;
        __syncthreads();
        if (tid < 128) {
            adjw[tid] = g_adjbits[(i0 + tid) * (N_NODES / 32) + (j0c >> 5)];
            u1s[tid] = g_u1T[(hg * 4 + (tid >> 5)) * N_NODES + j0c + (tid & 31)];
        } else {
            int q = tid - 128;
            u2s[q] = g_u2T[(hg * 4 + (q >> 5)) * N_NODES + j0c + (q & 31)];
        }
        __syncthreads();

#pragma unroll
        for (int kstep = 0; kstep < 2; kstep++) {
            const int jg = (j0c >> 4) + kstep;
            uint2 bh[5];
            const long bbase = ((long)(hglob * 128 + jg) * 5) * 32 + lane;
#pragma unroll
            for (int nf = 0; nf < 5; nf++) bh[nf] = g_bfragHI[bbase + nf * 32];

            const int jb = kstep * 16 + kq;
            float u1_0 = u1s[hloc * 32 + jb + 0];
            float u1_1 = u1s[hloc * 32 + jb + 1];
            float u1_8 = u1s[hloc * 32 + jb + 8];
            float u1_9 = u1s[hloc * 32 + jb + 9];
            float u2_0 = u2s[hloc * 32 + jb + 0];
            float u2_1 = u2s[hloc * 32 + jb + 1];
            float u2_8 = u2s[hloc * 32 + jb + 8];
            float u2_9 = u2s[hloc * 32 + jb + 9];

#pragma unroll
            for (int mf = 0; mf < 4; mf++) {
                uint32_t aw0 = adjw[ihalf + mf * 16 + rq];
                uint32_t aw1 = adjw[ihalf + mf * 16 + rq + 8];
                uint32_t areg[4];
#pragma unroll
                for (int rowsel = 0; rowsel < 2; rowsel++) {
                    float e1 = e1r[mf][rowsel], e2 = e2r[mf][rowsel], th = thr[mf][rowsel];
                    uint32_t aw = rowsel ? aw1 : aw0;
                    float w0 = (u1_0 >= th) ? u1_0 * e1 : u2_0 * e2;
                    float w1 = (u1_1 >= th) ? u1_1 * e1 : u2_1 * e2;
                    float w8 = (u1_8 >= th) ? u1_8 * e1 : u2_8 * e2;
                    float w9 = (u1_9 >= th) ? u1_9 * e1 : u2_9 * e2;
                    w0 = ((aw >> (jb + 0)) & 1) ? w0 : 0.f;
                    w1 = ((aw >> (jb + 1)) & 1) ? w1 : 0.f;
                    w8 = ((aw >> (jb + 8)) & 1) ? w8 : 0.f;
                    w9 = ((aw >> (jb + 9)) & 1) ? w9 : 0.f;
                    areg[rowsel]     = h2u(__floats2half2_rn(w0, w1));
                    areg[rowsel + 2] = h2u(__floats2half2_rn(w8, w9));
                }
#pragma unroll
                for (int nf = 0; nf < 5; nf++) mma16816(acc[mf][nf], areg, bh[nf]);
            }
        }
    }

#pragma unroll
    for (int mf = 0; mf < 4; mf++) {
        int r0 = i0 + ihalf + mf * 16 + rq;
        int r1 = r0 + 8;
#pragma unroll
        for (int nf = 0; nf < 4; nf++) {
            int f = nf * 8 + kq;
            *(float2*)&g_pnum[sp][r0 * GDIM + hglob * NF + f] =
                make_float2(acc[mf][nf][0], acc[mf][nf][1]);
            *(float2*)&g_pnum[sp][r1 * GDIM + hglob * NF + f] =
                make_float2(acc[mf][nf][2], acc[mf][nf][3]);
        }
        if ((lane & 3) == 0) {
            g_pz[sp][r0 * NH + hglob] = acc[mf][4][0];
            g_pz[sp][r1 * NH + hglob] = acc[mf][4][2];
        }
    }
}

// ---------------- K6: combine + normalize (float4/thread) ----------------
__global__ __launch_bounds__(256) void norm_kernel(float* __restrict__ out) {
    const int idx4 = (blockIdx.x * 256 + threadIdx.x) * 4;
    const int ih = idx4 >> 5;
    float4 num = make_float4(0.f, 0.f, 0.f, 0.f);
    float z = 0.f;
#pragma unroll
    for (int s = 0; s < NSPLIT; s++) {
        float4 v = *(const float4*)&g_pnum[s][idx4];
        num.x += v.x; num.y += v.y; num.z += v.z; num.w += v.w;
        z += g_pz[s][ih];
    }
    float inv = 1.0f / z;
    *(float4*)&out[idx4] = make_float4(num.x * inv, num.y * inv, num.z * inv, num.w * inv);
}

extern "C" void kernel_launch(void* const* d_in, const int* in_sizes, int n_in,
                              void* d_out, int out_size) {
    const float* h_ptr = nullptr;
    const int*   adj   = nullptr;
    const float* W_ptr = nullptr;
    const float* a_ptr = nullptr;
    for (int i = 0; i < n_in; i++) {
        long sz = in_sizes[i];
        if (sz == (long)N_NODES * IN_F)          h_ptr = (const float*)d_in[i];
        else if (sz == (long)N_NODES * N_NODES)  adj   = (const int*)d_in[i];
        else if (sz == (long)IN_F * GDIM)        W_ptr = (const float*)d_in[i];
        else if (sz == 2 * NF)                   a_ptr = (const float*)d_in[i];
    }
    float* out = (float*)d_out;

    hgemm_kernel<<<dim3(GDIM / 64, N_NODES / 64), 128>>>(h_ptr, W_ptr);
    score_kernel<<<(N_NODES * NH) / 256, 256>>>(a_ptr);
    bfrag_kernel<<<(NH * 128 * 5 * 32) / 256, 256>>>();
    adjbits_kernel<<<(N_NODES * N_NODES) / 256, 256>>>(adj);
    attn_kernel<<<dim3(N_NODES / 128, 2, NSPLIT), 256>>>();
    norm_kernel<<<(N_NODES * GDIM) / 1024, 256>>>(out);
}

// round 8
// speedup vs baseline: 3.0870x; 1.1351x over previous
#include <cuda_runtime.h>
#include <cuda_fp16.h>
#include <cuda_bf16.h>
#include <cstdint>

// GAT N=2048, IN=1024, H=8, F=32, slope=0.2 — all-HMMA pipeline.
//  K1 hgemm:   g = h @ W, split-fp16 (hi/lo, 3 passes) HMMA, 256 thr/CTA
//  K2 score:   u1=exp(sr),u2=exp(.2sr),e1=exp(sl),e2=exp(.2sl),thr=exp(-sl), [h][node]
//  K3 bfrag:   pack gT fp16 (hi only) into mma B-fragment layout, 40 N-rows
//  K4 adjbits: adj int32 -> bitmask words, strided ballot (MLP=8)
//  K5 attn:    W built in A-fragment registers (no exp), mma.sync m16n8k16
//  K6 norm:    out = sum(num)/sum(Z), float4 per thread

#define N_NODES 2048
#define IN_F    1024
#define NH      8
#define NF      32
#define GDIM    256
#define NSPLIT  4
#define JSPAN   (N_NODES/NSPLIT)   // 512

__device__ float  g_g[N_NODES * GDIM];
__device__ float  g_u1T[NH * N_NODES];
__device__ float  g_u2T[NH * N_NODES];
__device__ float  g_e1T[NH * N_NODES];
__device__ float  g_e2T[NH * N_NODES];
__device__ float  g_thrT[NH * N_NODES];
__device__ uint2  g_bfragHI[NH * 128 * 5 * 32];
__device__ uint32_t g_adjbits[N_NODES * (N_NODES / 32)];
__device__ float  g_pnum[NSPLIT][N_NODES * GDIM];
__device__ float  g_pz[NSPLIT][N_NODES * NH];

__device__ __forceinline__ uint32_t h2u(__half2 v) { return *(uint32_t*)&v; }

__device__ __forceinline__ void mma16816(float* c, const uint32_t* a, const uint2 b) {
    asm volatile(
        "mma.sync.aligned.m16n8k16.row.col.f32.f16.f16.f32 "
        "{%0,%1,%2,%3}, {%4,%5,%6,%7}, {%8,%9}, {%0,%1,%2,%3};"
        : "+f"(c[0]), "+f"(c[1]), "+f"(c[2]), "+f"(c[3])
        : "r"(a[0]), "r"(a[1]), "r"(a[2]), "r"(a[3]), "r"(b.x), "r"(b.y));
}

// ---------------- K1: g = h @ W, split-fp16 HMMA (256 threads) ----------------
// CTA tile 64x64, K-chunk 32, 8 warps (2m x 4n), double-buffered fragment-native smem.
//   Ah/Al: [ksub2][mf4][lane32][reg4]  half2
//   Bh/Bl: [ksub2][nf8][lane32][reg2]  half2
__global__ __launch_bounds__(256) void hgemm_kernel(const float* __restrict__ A,
                                                    const float* __restrict__ B) {
    __shared__ __half2 Ah[2][2*4*32*4], Al[2][2*4*32*4];
    __shared__ __half2 Bh[2][2*8*32*2], Bl[2][2*8*32*2];

    const int tid = threadIdx.x, wid = tid >> 5, lane = tid & 31;
    const int bm = blockIdx.y << 6, bn = blockIdx.x << 6;
    const int wm = wid & 1, wn = wid >> 1;          // 2 x 4 warp grid

    // A loader: row = tid>>2 (0..63), kh = (tid&3)*8
    const int arow = tid >> 2, akh = (tid & 3) * 8;
    // B loader: kp = tid&15 (k=2kp,2kp+1), n4 = (tid>>4)*4
    const int bkp = tid & 15, bn4 = (tid >> 4) * 4;
    const int bksub = bkp >> 3, breg = (bkp >> 2) & 1, blq = bkp & 3;

    float fa[8], fb[8];
    auto ldgA = [&](int k0) {
        const float* p = &A[(bm + arow) * IN_F + k0 + akh];
        float4 v0 = *(const float4*)p;
        float4 v1 = *(const float4*)(p + 4);
        fa[0]=v0.x; fa[1]=v0.y; fa[2]=v0.z; fa[3]=v0.w;
        fa[4]=v1.x; fa[5]=v1.y; fa[6]=v1.z; fa[7]=v1.w;
    };
    auto ldgB = [&](int k0) {
        const float* p0 = &B[(k0 + 2*bkp) * GDIM + bn + bn4];
        float4 v0 = *(const float4*)p0;
        float4 v1 = *(const float4*)(p0 + GDIM);
        fb[0]=v0.x; fb[1]=v0.y; fb[2]=v0.z; fb[3]=v0.w;
        fb[4]=v1.x; fb[5]=v1.y; fb[6]=v1.z; fb[7]=v1.w;
    };
    auto sts = [&](int buf) {
        // A: 4 k-pairs
#pragma unroll
        for (int p = 0; p < 4; p++) {
            int kkl = akh + 2 * p;                 // 0..31
            float v0 = fa[2*p], v1 = fa[2*p + 1];
            __half hh0 = __float2half_rn(v0), hh1 = __float2half_rn(v1);
            __half hl0 = __float2half_rn(v0 - __half2float(hh0));
            __half hl1 = __float2half_rn(v1 - __half2float(hh1));
            int ksub = kkl >> 4, kk16 = kkl & 15;
            int reg = ((arow >> 3) & 1) + ((kk16 >= 8) ? 2 : 0);
            int ln  = (arow & 7) * 4 + ((kk16 & 7) >> 1);
            int idx = ((ksub * 4 + (arow >> 4)) * 32 + ln) * 4 + reg;
            Ah[buf][idx] = __halves2half2(hh0, hh1);
            Al[buf][idx] = __halves2half2(hl0, hl1);
        }
        // B: 4 n columns
#pragma unroll
        for (int n = 0; n < 4; n++) {
            int ng = bn4 + n;                      // 0..63
            float v0 = fb[n], v1 = fb[4 + n];
            __half hh0 = __float2half_rn(v0), hh1 = __float2half_rn(v1);
            __half hl0 = __float2half_rn(v0 - __half2float(hh0));
            __half hl1 = __float2half_rn(v1 - __half2float(hh1));
            int ln  = (ng & 7) * 4 + blq;
            int idx = ((bksub * 8 + (ng >> 3)) * 32 + ln) * 2 + breg;
            Bh[buf][idx] = __halves2half2(hh0, hh1);
            Bl[buf][idx] = __halves2half2(hl0, hl1);
        }
    };

    float acc[2][2][4];
#pragma unroll
    for (int mf = 0; mf < 2; mf++)
#pragma unroll
        for (int nf = 0; nf < 2; nf++)
#pragma unroll
            for (int q = 0; q < 4; q++) acc[mf][nf][q] = 0.f;

    ldgA(0); ldgB(0);
    sts(0);

    for (int c = 0; c < IN_F / 32; c++) {
        __syncthreads();
        const int buf = c & 1;
        if (c + 1 < IN_F / 32) { ldgA((c + 1) * 32); ldgB((c + 1) * 32); }
#pragma unroll
        for (int ks = 0; ks < 2; ks++) {
            uint4 ahi[2], alo[2];
            uint2 bhi[2], blo[2];
#pragma unroll
            for (int mf = 0; mf < 2; mf++) {
                int idx = ((ks * 4 + wm * 2 + mf) * 32 + lane) * 4;
                ahi[mf] = *(uint4*)&Ah[buf][idx];
                alo[mf] = *(uint4*)&Al[buf][idx];
            }
#pragma unroll
            for (int nf = 0; nf < 2; nf++) {
                int idx = ((ks * 8 + wn * 2 + nf) * 32 + lane) * 2;
                bhi[nf] = *(uint2*)&Bh[buf][idx];
                blo[nf] = *(uint2*)&Bl[buf][idx];
            }
#pragma unroll
            for (int mf = 0; mf < 2; mf++) {
                uint32_t ah[4] = {ahi[mf].x, ahi[mf].y, ahi[mf].z, ahi[mf].w};
                uint32_t al[4] = {alo[mf].x, alo[mf].y, alo[mf].z, alo[mf].w};
#pragma unroll
                for (int nf = 0; nf < 2; nf++) {
                    mma16816(acc[mf][nf], ah, bhi[nf]);
                    mma16816(acc[mf][nf], ah, blo[nf]);
                    mma16816(acc[mf][nf], al, bhi[nf]);
                }
            }
        }
        if (c + 1 < IN_F / 32) sts((c + 1) & 1);
    }

    const int rq = lane >> 2, cq = (lane & 3) * 2;
#pragma unroll
    for (int mf = 0; mf < 2; mf++) {
        int r0 = bm + (wm * 2 + mf) * 16 + rq;
#pragma unroll
        for (int nf = 0; nf < 2; nf++) {
            int col = bn + (wn * 2 + nf) * 8 + cq;
            *(float2*)&g_g[r0 * GDIM + col] = make_float2(acc[mf][nf][0], acc[mf][nf][1]);
            *(float2*)&g_g[(r0 + 8) * GDIM + col] = make_float2(acc[mf][nf][2], acc[mf][nf][3]);
        }
    }
}

// ---------------- K2: score precompute (transposed) ----------------
__global__ __launch_bounds__(256) void score_kernel(const float* __restrict__ a) {
    __shared__ float as[2 * NF];
    if (threadIdx.x < 2 * NF) as[threadIdx.x] = a[threadIdx.x];
    __syncthreads();
    const int idx = blockIdx.x * 256 + threadIdx.x;   // node*8 + h
    const int node = idx >> 3, h = idx & 7;
    const float* gp = &g_g[idx * NF];
    float sl = 0.f, sr = 0.f;
#pragma unroll
    for (int c = 0; c < 8; c++) {
        float4 v = *(const float4*)&gp[c * 4];
        sl = fmaf(v.x, as[c*4+0], sl); sl = fmaf(v.y, as[c*4+1], sl);
        sl = fmaf(v.z, as[c*4+2], sl); sl = fmaf(v.w, as[c*4+3], sl);
        sr = fmaf(v.x, as[NF+c*4+0], sr); sr = fmaf(v.y, as[NF+c*4+1], sr);
        sr = fmaf(v.z, as[NF+c*4+2], sr); sr = fmaf(v.w, as[NF+c*4+3], sr);
    }
    const int o = h * N_NODES + node;
    g_u1T[o]  = expf(sr);
    g_u2T[o]  = expf(0.2f * sr);
    g_e1T[o]  = expf(sl);
    g_e2T[o]  = expf(0.2f * sl);
    g_thrT[o] = expf(-sl);
}

// ---------------- K3: pack g into B-fragment layout (hi fp16) ----------------
__global__ __launch_bounds__(256) void bfrag_kernel() {
    int idx = blockIdx.x * 256 + threadIdx.x;          // < 163840
    int lane = idx & 31;
    int rem = idx >> 5;
    int nf = rem % 5; rem /= 5;
    int jg = rem & 127;
    int h  = rem >> 7;
    int n = lane >> 2;
    int f = nf * 8 + n;
    int kq = (lane & 3) * 2;
    int j0 = jg * 16;

    float v[4];
#pragma unroll
    for (int r = 0; r < 2; r++)
#pragma unroll
        for (int s = 0; s < 2; s++) {
            int j = j0 + r * 8 + kq + s;
            float val;
            if (f < NF)        val = g_g[j * GDIM + h * NF + f];
            else if (f == NF)  val = 1.0f;
            else               val = 0.0f;
            v[r * 2 + s] = val;
        }
    g_bfragHI[idx] = make_uint2(
        h2u(__halves2half2(__float2half_rn(v[0]), __float2half_rn(v[1]))),
        h2u(__halves2half2(__float2half_rn(v[2]), __float2half_rn(v[3]))));
}

// ---------------- K4: adjacency -> bitmask words (strided ballot, MLP=8) ----------------
__global__ __launch_bounds__(256) void adjbits_kernel(const int* __restrict__ adj) {
    const int w = blockIdx.x * 8 + (threadIdx.x >> 5);  // warp -> 8 words
    const int lane = threadIdx.x & 31;
    const long base = (long)w * 256;
    int v[8];
#pragma unroll
    for (int s = 0; s < 8; s++) v[s] = adj[base + s * 32 + lane];
    uint32_t m[8];
#pragma unroll
    for (int s = 0; s < 8; s++) m[s] = __ballot_sync(0xFFFFFFFFu, v[s] != 0);
    uint32_t out = m[0];
#pragma unroll
    for (int s = 1; s < 8; s++) out = (lane == s) ? m[s] : out;
    if (lane < 8) g_adjbits[w * 8 + lane] = out;
}

// ---------------- K5: HMMA attention aggregation ----------------
__global__ __launch_bounds__(256, 1) void attn_kernel() {
    __shared__ uint32_t adjw[128];
    __shared__ float u1s[128];   // [4 h][32 j]
    __shared__ float u2s[128];

    const int tid = threadIdx.x, wid = tid >> 5, lane = tid & 31;
    const int i0 = blockIdx.x * 128;
    const int hg = blockIdx.y;
    const int sp = blockIdx.z;
    const int j00 = sp * JSPAN;

    const int hloc  = wid >> 1;
    const int hglob = hg * 4 + hloc;
    const int ihalf = (wid & 1) * 64;
    const int rq = lane >> 2;
    const int kq = (lane & 3) * 2;

    float e1r[4][2], e2r[4][2], thr[4][2];
#pragma unroll
    for (int mf = 0; mf < 4; mf++) {
        int r = i0 + ihalf + mf * 16 + rq;
        e1r[mf][0] = g_e1T[hglob * N_NODES + r];
        e1r[mf][1] = g_e1T[hglob * N_NODES + r + 8];
        e2r[mf][0] = g_e2T[hglob * N_NODES + r];
        e2r[mf][1] = g_e2T[hglob * N_NODES + r + 8];
        thr[mf][0] = g_thrT[hglob * N_NODES + r];
        thr[mf][1] = g_thrT[hglob * N_NODES + r + 8];
    }

    float acc[4][5][4];
#pragma unroll
    for (int mf = 0; mf < 4; mf++)
#pragma unroll
        for (int nf = 0; nf < 5; nf++)
#pragma unroll
            for (int q = 0; q < 4; q++) acc[mf][nf][q] = 0.f;

    for (int c = 0; c < 16; c++) {
        const int j0c = j00 + c * 32;
        // prefetch both ksteps' B fragments from gmem (independent of smem fills)
        uint2 bh[2][5];
#pragma unroll
        for (int ks = 0; ks < 2; ks++) {
            const long bbase = ((long)(hglob * 128 + (j0c >> 4) + ks) * 5) * 32 + lane;
#pragma unroll
            for (int nf = 0; nf < 5; nf++) bh[ks][nf] = g_bfragHI[bbase + nf * 32];
        }
        __syncthreads();
        if (tid < 128) {
            adjw[tid] = g_adjbits[(i0 + tid) * (N_NODES / 32) + (j0c >> 5)];
            u1s[tid] = g_u1T[(hg * 4 + (tid >> 5)) * N_NODES + j0c + (tid & 31)];
        } else {
            int q = tid - 128;
            u2s[q] = g_u2T[(hg * 4 + (q >> 5)) * N_NODES + j0c + (q & 31)];
        }
        __syncthreads();

#pragma unroll
        for (int kstep = 0; kstep < 2; kstep++) {
            const int jb = kstep * 16 + kq;
            float u1_0 = u1s[hloc * 32 + jb + 0];
            float u1_1 = u1s[hloc * 32 + jb + 1];
            float u1_8 = u1s[hloc * 32 + jb + 8];
            float u1_9 = u1s[hloc * 32 + jb + 9];
            float u2_0 = u2s[hloc * 32 + jb + 0];
            float u2_1 = u2s[hloc * 32 + jb + 1];
            float u2_8 = u2s[hloc * 32 + jb + 8];
            float u2_9 = u2s[hloc * 32 + jb + 9];

#pragma unroll
            for (int mf = 0; mf < 4; mf++) {
                uint32_t aw0 = adjw[ihalf + mf * 16 + rq];
                uint32_t aw1 = adjw[ihalf + mf * 16 + rq + 8];
                uint32_t areg[4];
#pragma unroll
                for (int rowsel = 0; rowsel < 2; rowsel++) {
                    float e1 = e1r[mf][rowsel], e2 = e2r[mf][rowsel], th = thr[mf][rowsel];
                    uint32_t aw = rowsel ? aw1 : aw0;
                    float w0 = (u1_0 >= th) ? u1_0 * e1 : u2_0 * e2;
                    float w1 = (u1_1 >= th) ? u1_1 * e1 : u2_1 * e2;
                    float w8 = (u1_8 >= th) ? u1_8 * e1 : u2_8 * e2;
                    float w9 = (u1_9 >= th) ? u1_9 * e1 : u2_9 * e2;
                    w0 = ((aw >> (jb + 0)) & 1) ? w0 : 0.f;
                    w1 = ((aw >> (jb + 1)) & 1) ? w1 : 0.f;
                    w8 = ((aw >> (jb + 8)) & 1) ? w8 : 0.f;
                    w9 = ((aw >> (jb + 9)) & 1) ? w9 : 0.f;
                    areg[rowsel]     = h2u(__floats2half2_rn(w0, w1));
                    areg[rowsel + 2] = h2u(__floats2half2_rn(w8, w9));
                }
#pragma unroll
                for (int nf = 0; nf < 5; nf++) mma16816(acc[mf][nf], areg, bh[kstep][nf]);
            }
        }
    }

#pragma unroll
    for (int mf = 0; mf < 4; mf++) {
        int r0 = i0 + ihalf + mf * 16 + rq;
        int r1 = r0 + 8;
#pragma unroll
        for (int nf = 0; nf < 4; nf++) {
            int f = nf * 8 + kq;
            *(float2*)&g_pnum[sp][r0 * GDIM + hglob * NF + f] =
                make_float2(acc[mf][nf][0], acc[mf][nf][1]);
            *(float2*)&g_pnum[sp][r1 * GDIM + hglob * NF + f] =
                make_float2(acc[mf][nf][2], acc[mf][nf][3]);
        }
        if ((lane & 3) == 0) {
            g_pz[sp][r0 * NH + hglob] = acc[mf][4][0];
            g_pz[sp][r1 * NH + hglob] = acc[mf][4][2];
        }
    }
}

// ---------------- K6: combine + normalize (float4/thread) ----------------
__global__ __launch_bounds__(256) void norm_kernel(float* __restrict__ out) {
    const int idx4 = (blockIdx.x * 256 + threadIdx.x) * 4;
    const int ih = idx4 >> 5;
    float4 num = make_float4(0.f, 0.f, 0.f, 0.f);
    float z = 0.f;
#pragma unroll
    for (int s = 0; s < NSPLIT; s++) {
        float4 v = *(const float4*)&g_pnum[s][idx4];
        num.x += v.x; num.y += v.y; num.z += v.z; num.w += v.w;
        z += g_pz[s][ih];
    }
    float inv = 1.0f / z;
    *(float4*)&out[idx4] = make_float4(num.x * inv, num.y * inv, num.z * inv, num.w * inv);
}

extern "C" void kernel_launch(void* const* d_in, const int* in_sizes, int n_in,
                              void* d_out, int out_size) {
    const float* h_ptr = nullptr;
    const int*   adj   = nullptr;
    const float* W_ptr = nullptr;
    const float* a_ptr = nullptr;
    for (int i = 0; i < n_in; i++) {
        long sz = in_sizes[i];
        if (sz == (long)N_NODES * IN_F)          h_ptr = (const float*)d_in[i];
        else if (sz == (long)N_NODES * N_NODES)  adj   = (const int*)d_in[i];
        else if (sz == (long)IN_F * GDIM)        W_ptr = (const float*)d_in[i];
        else if (sz == 2 * NF)                   a_ptr = (const float*)d_in[i];
    }
    float* out = (float*)d_out;

    adjbits_kernel<<<(N_NODES * (N_NODES / 32)) / 64, 256>>>(adj);
    hgemm_kernel<<<dim3(GDIM / 64, N_NODES / 64), 256>>>(h_ptr, W_ptr);
    score_kernel<<<(N_NODES * NH) / 256, 256>>>(a_ptr);
    bfrag_kernel<<<(NH * 128 * 5 * 32) / 256, 256>>>();
    attn_kernel<<<dim3(N_NODES / 128, 2, NSPLIT), 256>>>();
    norm_kernel<<<(N_NODES * GDIM) / 1024, 256>>>(out);
}